// round 5
// baseline (speedup 1.0000x reference)
#include <cuda_runtime.h>
#include <cuda_fp16.h>
#include <cstdint>

// LSTM scan, fused persistent kernel (double-buffered activations, 1 barrier/step).
// B=4096 batch rows, T=512 steps, D=64 input, H=128 hidden, 4H=512 gates.
// Design:
//  - 128 CTAs x 256 threads; each CTA owns BTILE=32 batch rows for ALL 512 steps
//    (recurrence is independent per batch row -> zero inter-CTA communication).
//  - Wcat = [W_ih | W_hh] as fp16 in shared memory: [512 gates][192+pad] (~200KB).
//  - Per step: gates[32,512] = A[32,192] @ Wcat^T via mma.sync.m16n8k16 f16/f32.
//  - A is DOUBLE-BUFFERED: step t reads A[t%2], epilogue writes h_t and x_{t+1}
//    into A[(t+1)%2] -> only ONE __syncthreads per step (the end-of-step one).
//    Fast warps start the MUFU-heavy epilogue while slow warps finish MMAs.
//  - fp32 cell state in registers; exact EX2-based sigmoid/tanh (precision:
//    fp16 operands + fp32 accum -> predicted rel_err ~3e-4 < 1e-3).
//  - x_{t+1} prefetched from global at the top of each step (clamped, branchless).

namespace {
constexpr int T_STEPS  = 512;
constexpr int DIM_D    = 64;
constexpr int DIM_H    = 128;
constexpr int G4       = 512;   // 4*H gate rows
constexpr int KDIM     = 192;   // D + H
constexpr int KP       = 200;   // padded row length in halves (400B = odd*16B -> conflict-free ldmatrix)
constexpr int BTILE    = 32;
constexpr int NTHREADS = 256;   // 8 warps
constexpr int NBLOCKS  = 128;   // 4096 / 32
constexpr int ABUF     = BTILE * KP;                     // halves per A buffer
constexpr int SMEM_BYTES = (G4 * KP + 2 * ABUF) * 2;     // 230400 B < 232448 cap
}

__device__ __forceinline__ uint32_t smem_u32(const void* p) {
    return static_cast<uint32_t>(__cvta_generic_to_shared(p));
}

// Bitcast half2 -> u32 (no library intrinsic for this; reinterpret is free).
__device__ __forceinline__ uint32_t h2_u32(__half2 h) {
    return *reinterpret_cast<const uint32_t*>(&h);
}

// Accurate (EX2-based) activations: MUFU.EX2 + MUFU.RCP, ~1e-6 error,
// clamped so exp never overflows to inf.
__device__ __forceinline__ float sigmoid_acc(float x) {
    x = fminf(fmaxf(x, -30.f), 30.f);
    return __fdividef(1.f, 1.f + __expf(-x));
}
__device__ __forceinline__ float tanh_acc(float x) {
    x = fminf(fmaxf(x, -15.f), 15.f);
    float e = __expf(-2.f * x);
    return __fdividef(1.f - e, 1.f + e);
}

__global__ void __launch_bounds__(NTHREADS, 1)
lstm_fused_kernel(const float* __restrict__ state,
                  const float* __restrict__ W_ih,
                  const float* __restrict__ W_hh,
                  const float* __restrict__ b_ih,
                  const float* __restrict__ b_hh,
                  const float* __restrict__ W_fc,
                  const float* __restrict__ b_fc,
                  float* __restrict__ out)
{
    extern __shared__ __half sm[];
    __half* Wsm  = sm;                  // [G4][KP] fp16 concat weights
    __half* Asm0 = sm + G4 * KP;        // A buffer 0: [BTILE][KP]
    __half* Asm1 = Asm0 + ABUF;         // A buffer 1: [BTILE][KP]

    const int tid  = threadIdx.x;
    const int w    = tid >> 5;    // warp id 0..7
    const int lane = tid & 31;
    const int b0   = blockIdx.x * BTILE;

    // ---- Prologue: weights -> smem fp16; zero A buffers (h0 = 0) ----
    for (int idx = tid; idx < G4 * KDIM; idx += NTHREADS) {
        int n = idx / KDIM;
        int k = idx - n * KDIM;
        float v = (k < DIM_D) ? W_ih[n * DIM_D + k] : W_hh[n * DIM_H + (k - DIM_D)];
        Wsm[n * KP + k] = __float2half_rn(v);
    }
    for (int idx = tid; idx < 2 * ABUF; idx += NTHREADS)
        Asm0[idx] = __ushort_as_half((unsigned short)0);

    // x-loader role: thread -> (row = tid/8, 8-float segment = tid%8)
    const int xrow = tid >> 3;
    const int xc8  = tid & 7;
    const float* xbase = state + (size_t)(b0 + xrow) * T_STEPS * DIM_D + xc8 * 8;

    __syncthreads();

    // x_0 into A buffer 0 (step 0 reads buf0)
    {
        float4 v0 = *(const float4*)(xbase);
        float4 v1 = *(const float4*)(xbase + 4);
        __half2* dst = (__half2*)&Asm0[xrow * KP + xc8 * 8];
        dst[0] = __floats2half2_rn(v0.x, v0.y);
        dst[1] = __floats2half2_rn(v0.z, v0.w);
        dst[2] = __floats2half2_rn(v1.x, v1.y);
        dst[3] = __floats2half2_rn(v1.z, v1.w);
    }

    // Per-thread bias for its accumulator columns.
    // n-tile j (0..7): gate type gt = j>>1 (i,f,g,o), sub s = j&1:
    //   n_base(j) = 128*gt + 16*w + 8*s ; thread cols = n_base + 2*(lane&3) + {0,1}
    float biasr[8][2];
    #pragma unroll
    for (int j = 0; j < 8; ++j) {
        int nb = (j >> 1) * 128 + 16 * w + (j & 1) * 8 + 2 * (lane & 3);
        biasr[j][0] = b_ih[nb]     + b_hh[nb];
        biasr[j][1] = b_ih[nb + 1] + b_hh[nb + 1];
    }

    // ldmatrix source addresses, per A buffer (lane-dependent, +32B per k-tile)
    uint32_t aAddr[2][2], bAddr[8];
    uint32_t hBase[2];   // epilogue h-write base per buffer
    uint32_t xBase[2];   // x-store base per buffer
    {
        int ar = (lane & 7) + ((lane >> 3) & 1) * 8;   // rows 0..15 pattern
        int ac = (lane >> 4) * 8;                      // col half-split
        aAddr[0][0] = smem_u32(&Asm0[ar * KP + ac]);
        aAddr[0][1] = smem_u32(&Asm0[(16 + ar) * KP + ac]);
        aAddr[1][0] = smem_u32(&Asm1[ar * KP + ac]);
        aAddr[1][1] = smem_u32(&Asm1[(16 + ar) * KP + ac]);
        hBase[0] = smem_u32(Asm0);
        hBase[1] = smem_u32(Asm1);
        xBase[0] = smem_u32(&Asm0[xrow * KP + xc8 * 8]);
        xBase[1] = smem_u32(&Asm1[xrow * KP + xc8 * 8]);
        int br = lane & 7;
        int bc = ((lane >> 3) & 1) * 8;
        #pragma unroll
        for (int j = 0; j < 8; ++j) {
            int nb0 = (j >> 1) * 128 + 16 * w + (j & 1) * 8;
            bAddr[j] = smem_u32(&Wsm[(nb0 + br) * KP + bc]);
        }
    }

    // fp32 cell state, 16 elems/thread: index (mi*8 + s*4 + rh*2 + c)
    float cst[16];
    #pragma unroll
    for (int i = 0; i < 16; ++i) cst[i] = 0.f;

    __syncthreads();

    // ---- Time loop: read A[t&1], write A[(t+1)&1]; ONE barrier per step ----
    #pragma unroll 1
    for (int t = 0; t < T_STEPS; ++t) {
        const int rb = t & 1;         // read buffer
        const int wb = rb ^ 1;        // write buffer

        // Prefetch x_{t+1} (clamped, branchless load; stored in the epilogue)
        const bool havex = (t < T_STEPS - 1);
        const int  tn    = havex ? (t + 1) : t;
        const float* xp  = xbase + (size_t)tn * DIM_D;
        float4 xv0 = *(const float4*)(xp);
        float4 xv1 = *(const float4*)(xp + 4);

        // Accumulators init from bias (rows share column bias)
        float acc[2][8][4];
        #pragma unroll
        for (int mi = 0; mi < 2; ++mi)
            #pragma unroll
            for (int j = 0; j < 8; ++j) {
                acc[mi][j][0] = biasr[j][0];
                acc[mi][j][1] = biasr[j][1];
                acc[mi][j][2] = biasr[j][0];
                acc[mi][j][3] = biasr[j][1];
            }

        // gates = A @ Wcat^T, K = 192 in 12 k-tiles of 16
        #pragma unroll
        for (int kt = 0; kt < 12; ++kt) {
            uint32_t a0[4], a1[4];
            asm volatile("ldmatrix.sync.aligned.m8n8.x4.shared.b16 {%0,%1,%2,%3}, [%4];"
                         : "=r"(a0[0]), "=r"(a0[1]), "=r"(a0[2]), "=r"(a0[3])
                         : "r"(aAddr[rb][0] + kt * 32));
            asm volatile("ldmatrix.sync.aligned.m8n8.x4.shared.b16 {%0,%1,%2,%3}, [%4];"
                         : "=r"(a1[0]), "=r"(a1[1]), "=r"(a1[2]), "=r"(a1[3])
                         : "r"(aAddr[rb][1] + kt * 32));
            #pragma unroll
            for (int j = 0; j < 8; ++j) {
                uint32_t bb[2];
                asm volatile("ldmatrix.sync.aligned.m8n8.x2.shared.b16 {%0,%1}, [%2];"
                             : "=r"(bb[0]), "=r"(bb[1])
                             : "r"(bAddr[j] + kt * 32));
                asm volatile("mma.sync.aligned.m16n8k16.row.col.f32.f16.f16.f32 "
                             "{%0,%1,%2,%3},{%4,%5,%6,%7},{%8,%9},{%0,%1,%2,%3};"
                             : "+f"(acc[0][j][0]), "+f"(acc[0][j][1]),
                               "+f"(acc[0][j][2]), "+f"(acc[0][j][3])
                             : "r"(a0[0]), "r"(a0[1]), "r"(a0[2]), "r"(a0[3]),
                               "r"(bb[0]), "r"(bb[1]));
                asm volatile("mma.sync.aligned.m16n8k16.row.col.f32.f16.f16.f32 "
                             "{%0,%1,%2,%3},{%4,%5,%6,%7},{%8,%9},{%0,%1,%2,%3};"
                             : "+f"(acc[1][j][0]), "+f"(acc[1][j][1]),
                               "+f"(acc[1][j][2]), "+f"(acc[1][j][3])
                             : "r"(a1[0]), "r"(a1[1]), "r"(a1[2]), "r"(a1[3]),
                               "r"(bb[0]), "r"(bb[1]));
            }
        }

        // NO barrier here: epilogue writes go to the OTHER buffer. A warp can
        // only reach step t+1's epilogue (writing buf rb) after the end-of-step
        // barrier below, which guarantees all step-t reads of buf rb are done.

        // Epilogue: LSTM cell in fp32, write h_t (fp16) into A[wb] cols 64..191.
        // i/f/g/o for a unit live at the same fragment slot in n-tiles s, 2+s, 4+s, 6+s.
        #pragma unroll
        for (int mi = 0; mi < 2; ++mi)
        #pragma unroll
        for (int s = 0; s < 2; ++s)
        #pragma unroll
        for (int rh = 0; rh < 2; ++rh) {
            float hv[2];
            #pragma unroll
            for (int c = 0; c < 2; ++c) {
                int q = rh * 2 + c;
                float iv = sigmoid_acc(acc[mi][0 + s][q]);
                float fv = sigmoid_acc(acc[mi][2 + s][q]);
                float gv = tanh_acc   (acc[mi][4 + s][q]);
                float ov = sigmoid_acc(acc[mi][6 + s][q]);
                int ci = mi * 8 + s * 4 + rh * 2 + c;
                float cn = fv * cst[ci] + iv * gv;
                cst[ci] = cn;
                hv[c] = ov * tanh_acc(cn);
            }
            int row  = 16 * mi + (lane >> 2) + 8 * rh;
            int colh = 64 + 16 * w + 8 * s + 2 * (lane & 3);
            uint32_t addr = hBase[wb] + (row * KP + colh) * 2;
            uint32_t pk = h2_u32(__floats2half2_rn(hv[0], hv[1]));
            asm volatile("st.shared.b32 [%0], %1;" :: "r"(addr), "r"(pk));
        }

        // Store prefetched x_{t+1} into A[wb]
        if (havex) {
            uint32_t p0 = h2_u32(__floats2half2_rn(xv0.x, xv0.y));
            uint32_t p1 = h2_u32(__floats2half2_rn(xv0.z, xv0.w));
            uint32_t p2 = h2_u32(__floats2half2_rn(xv1.x, xv1.y));
            uint32_t p3 = h2_u32(__floats2half2_rn(xv1.z, xv1.w));
            asm volatile("st.shared.v4.b32 [%0], {%1,%2,%3,%4};"
                         :: "r"(xBase[wb]), "r"(p0), "r"(p1), "r"(p2), "r"(p3));
        }

        __syncthreads();  // h_t / x_{t+1} in A[wb] visible for next step
    }

    // ---- Final projection: out[b, 0:8] = tanh(h @ W_fc^T + b_fc) ----
    // After t=511 (rb=1, wb=0), h_T sits fp16 in Asm0 cols 64..191.
    {
        int row = tid >> 3;   // 32 rows
        int a   = tid & 7;    // 8 outputs
        float accp = b_fc[a];
        const float* wf = W_fc + a * DIM_H;
        #pragma unroll 8
        for (int u = 0; u < DIM_H; ++u)
            accp += __half2float(Asm0[row * KP + 64 + u]) * wf[u];
        out[(size_t)(b0 + row) * 8 + a] = tanhf(accp);
    }
}

extern "C" void kernel_launch(void* const* d_in, const int* in_sizes, int n_in,
                              void* d_out, int out_size) {
    const float* state = (const float*)d_in[0];
    const float* W_ih  = (const float*)d_in[1];
    const float* W_hh  = (const float*)d_in[2];
    const float* b_ih  = (const float*)d_in[3];
    const float* b_hh  = (const float*)d_in[4];
    const float* W_fc  = (const float*)d_in[5];
    const float* b_fc  = (const float*)d_in[6];
    float* out = (float*)d_out;

    // Opt-in to >48KB dynamic shared memory (idempotent; not a stream op, so
    // graph-capture safe).
    cudaFuncSetAttribute(lstm_fused_kernel,
                         cudaFuncAttributeMaxDynamicSharedMemorySize, SMEM_BYTES);

    lstm_fused_kernel<<<NBLOCKS, NTHREADS, SMEM_BYTES>>>(
        state, W_ih, W_hh, b_ih, b_hh, W_fc, b_fc, out);
}

// round 12
// speedup vs baseline: 1.0552x; 1.0552x over previous
#include <cuda_runtime.h>
#include <cuda_fp16.h>
#include <cstdint>

// LSTM scan, fused persistent kernel. v3b: 512 threads / 16 warps per CTA,
// B-fragment loads batched ahead of MMAs (asm volatile preserves order, so
// the old LDSM->MMA->LDSM->MMA sequence serialized on LDS latency).
// Round-5 ncu (v2, 8 warps): occ=12.5%, issue=38.8%, tensor=38.5% ->
// latency-bound. Fix: double warps per SM + decouple LDSM from MMA issue.
//
// B=4096, T=512, D=64, H=128, 4H=512.
//  - 128 CTAs x 512 threads; each CTA owns BTILE=32 batch rows for all steps.
//  - Wcat=[W_ih|W_hh] fp16 in smem [512][200]; A=[x|h] double-buffered,
//    ONE __syncthreads per step (read A[t&1], write A[(t+1)&1]).
//  - gates[32,512] = A[32,192] @ Wcat^T via mma.sync.m16n8k16 f16/f32.
//  - fp32 cell state in regs; exact EX2-based sigmoid/tanh.

namespace {
constexpr int T_STEPS  = 512;
constexpr int DIM_D    = 64;
constexpr int DIM_H    = 128;
constexpr int G4       = 512;
constexpr int KDIM     = 192;
constexpr int KP       = 200;   // padded row (400B, odd*16B -> conflict-free ldmatrix)
constexpr int BTILE    = 32;
constexpr int NTHREADS = 512;   // 16 warps
constexpr int NBLOCKS  = 128;
constexpr int ABUF     = BTILE * KP;
constexpr int SMEM_BYTES = (G4 * KP + 2 * ABUF) * 2;  // 230400 B < 232448 cap
}

__device__ __forceinline__ uint32_t smem_u32(const void* p) {
    return static_cast<uint32_t>(__cvta_generic_to_shared(p));
}
__device__ __forceinline__ uint32_t h2_u32(__half2 h) {
    return *reinterpret_cast<const uint32_t*>(&h);
}
__device__ __forceinline__ float sigmoid_acc(float x) {
    x = fminf(fmaxf(x, -30.f), 30.f);
    return __fdividef(1.f, 1.f + __expf(-x));
}
__device__ __forceinline__ float tanh_acc(float x) {
    x = fminf(fmaxf(x, -15.f), 15.f);
    float e = __expf(-2.f * x);
    return __fdividef(1.f - e, 1.f + e);
}

__global__ void __launch_bounds__(NTHREADS, 1)
lstm_fused_kernel(const float* __restrict__ state,
                  const float* __restrict__ W_ih,
                  const float* __restrict__ W_hh,
                  const float* __restrict__ b_ih,
                  const float* __restrict__ b_hh,
                  const float* __restrict__ W_fc,
                  const float* __restrict__ b_fc,
                  float* __restrict__ out)
{
    extern __shared__ __half sm[];
    __half* Wsm  = sm;             // [G4][KP]
    __half* Asm0 = sm + G4 * KP;   // [BTILE][KP]
    __half* Asm1 = Asm0 + ABUF;

    const int tid  = threadIdx.x;
    const int w    = tid >> 5;     // warp 0..15
    const int lane = tid & 31;
    const int b0   = blockIdx.x * BTILE;

    // ---- Prologue: weights -> smem fp16; zero both A buffers ----
    for (int idx = tid; idx < G4 * KDIM; idx += NTHREADS) {
        int n = idx / KDIM;
        int k = idx - n * KDIM;
        float v = (k < DIM_D) ? W_ih[n * DIM_D + k] : W_hh[n * DIM_H + (k - DIM_D)];
        Wsm[n * KP + k] = __float2half_rn(v);
    }
    for (int idx = tid; idx < 2 * ABUF; idx += NTHREADS)
        Asm0[idx] = __ushort_as_half((unsigned short)0);

    // x-loader role: 512 threads cover 32 rows x 16 segments of 4 floats
    const int xrow = tid >> 4;          // 0..31
    const int xs4  = tid & 15;          // 0..15
    const float* xbase = state + (size_t)(b0 + xrow) * T_STEPS * DIM_D + xs4 * 4;

    __syncthreads();

    // x_0 into A buffer 0
    {
        float4 v = *(const float4*)(xbase);
        __half2* dst = (__half2*)&Asm0[xrow * KP + xs4 * 4];
        dst[0] = __floats2half2_rn(v.x, v.y);
        dst[1] = __floats2half2_rn(v.z, v.w);
    }

    // Per-thread bias: n-tile j = gate type (i,f,g,o); n_base(j) = 128*j + 8*w
    float biasr[4][2];
    #pragma unroll
    for (int j = 0; j < 4; ++j) {
        int nb = j * 128 + 8 * w + 2 * (lane & 3);
        biasr[j][0] = b_ih[nb]     + b_hh[nb];
        biasr[j][1] = b_ih[nb + 1] + b_hh[nb + 1];
    }

    // ldmatrix addresses
    uint32_t aAddr[2][2], bAddr[4];
    uint32_t hBase[2], xBase[2];
    {
        int ar = (lane & 7) + ((lane >> 3) & 1) * 8;
        int ac = (lane >> 4) * 8;
        aAddr[0][0] = smem_u32(&Asm0[ar * KP + ac]);
        aAddr[0][1] = smem_u32(&Asm0[(16 + ar) * KP + ac]);
        aAddr[1][0] = smem_u32(&Asm1[ar * KP + ac]);
        aAddr[1][1] = smem_u32(&Asm1[(16 + ar) * KP + ac]);
        hBase[0] = smem_u32(Asm0);
        hBase[1] = smem_u32(Asm1);
        xBase[0] = smem_u32(&Asm0[xrow * KP + xs4 * 4]);
        xBase[1] = smem_u32(&Asm1[xrow * KP + xs4 * 4]);
        int br = lane & 7;
        int bc = ((lane >> 3) & 1) * 8;
        #pragma unroll
        for (int j = 0; j < 4; ++j) {
            int nb0 = j * 128 + 8 * w;
            bAddr[j] = smem_u32(&Wsm[(nb0 + br) * KP + bc]);
        }
    }

    // fp32 cell state, 8 elems/thread: index (mi*4 + rh*2 + c)
    float cst[8];
    #pragma unroll
    for (int i = 0; i < 8; ++i) cst[i] = 0.f;

    __syncthreads();

    // ---- Time loop: read A[t&1], write A[(t+1)&1]; ONE barrier per step ----
    #pragma unroll 1
    for (int t = 0; t < T_STEPS; ++t) {
        const int rb = t & 1;
        const int wb = rb ^ 1;

        // Prefetch x_{t+1} (clamped, branchless; stored in epilogue)
        const bool havex = (t < T_STEPS - 1);
        const int  tn    = havex ? (t + 1) : t;
        float4 xv = *(const float4*)(xbase + (size_t)tn * DIM_D);

        // Accumulators from bias
        float acc[2][4][4];
        #pragma unroll
        for (int mi = 0; mi < 2; ++mi)
            #pragma unroll
            for (int j = 0; j < 4; ++j) {
                acc[mi][j][0] = biasr[j][0];
                acc[mi][j][1] = biasr[j][1];
                acc[mi][j][2] = biasr[j][0];
                acc[mi][j][3] = biasr[j][1];
            }

        // gates = A @ Wcat^T, K=192 in 12 k-tiles.
        // All 6 LDSMs issued before the 8 MMAs (asm volatile keeps program
        // order, so batching the loads is what lets HMMA overlap LDS latency).
        #pragma unroll
        for (int kt = 0; kt < 12; ++kt) {
            uint32_t a0[4], a1[4], bb[4][2];
            asm volatile("ldmatrix.sync.aligned.m8n8.x4.shared.b16 {%0,%1,%2,%3}, [%4];"
                         : "=r"(a0[0]), "=r"(a0[1]), "=r"(a0[2]), "=r"(a0[3])
                         : "r"(aAddr[rb][0] + kt * 32));
            asm volatile("ldmatrix.sync.aligned.m8n8.x4.shared.b16 {%0,%1,%2,%3}, [%4];"
                         : "=r"(a1[0]), "=r"(a1[1]), "=r"(a1[2]), "=r"(a1[3])
                         : "r"(aAddr[rb][1] + kt * 32));
            #pragma unroll
            for (int j = 0; j < 4; ++j)
                asm volatile("ldmatrix.sync.aligned.m8n8.x2.shared.b16 {%0,%1}, [%2];"
                             : "=r"(bb[j][0]), "=r"(bb[j][1])
                             : "r"(bAddr[j] + kt * 32));
            #pragma unroll
            for (int j = 0; j < 4; ++j) {
                asm volatile("mma.sync.aligned.m16n8k16.row.col.f32.f16.f16.f32 "
                             "{%0,%1,%2,%3},{%4,%5,%6,%7},{%8,%9},{%0,%1,%2,%3};"
                             : "+f"(acc[0][j][0]), "+f"(acc[0][j][1]),
                               "+f"(acc[0][j][2]), "+f"(acc[0][j][3])
                             : "r"(a0[0]), "r"(a0[1]), "r"(a0[2]), "r"(a0[3]),
                               "r"(bb[j][0]), "r"(bb[j][1]));
                asm volatile("mma.sync.aligned.m16n8k16.row.col.f32.f16.f16.f32 "
                             "{%0,%1,%2,%3},{%4,%5,%6,%7},{%8,%9},{%0,%1,%2,%3};"
                             : "+f"(acc[1][j][0]), "+f"(acc[1][j][1]),
                               "+f"(acc[1][j][2]), "+f"(acc[1][j][3])
                             : "r"(a1[0]), "r"(a1[1]), "r"(a1[2]), "r"(a1[3]),
                               "r"(bb[j][0]), "r"(bb[j][1]));
            }
        }

        // No mid-step barrier: writes go to the other buffer; the end-of-step
        // barrier of step t-1 ordered all reads of buf wb before these writes.

        // Epilogue: j=0..3 are i,f,g,o directly. 8 units/thread.
        #pragma unroll
        for (int mi = 0; mi < 2; ++mi)
        #pragma unroll
        for (int rh = 0; rh < 2; ++rh) {
            float hv[2];
            #pragma unroll
            for (int c = 0; c < 2; ++c) {
                int q = rh * 2 + c;
                float iv = sigmoid_acc(acc[mi][0][q]);
                float fv = sigmoid_acc(acc[mi][1][q]);
                float gv = tanh_acc   (acc[mi][2][q]);
                float ov = sigmoid_acc(acc[mi][3][q]);
                int ci = mi * 4 + rh * 2 + c;
                float cn = fv * cst[ci] + iv * gv;
                cst[ci] = cn;
                hv[c] = ov * tanh_acc(cn);
            }
            int row  = 16 * mi + (lane >> 2) + 8 * rh;
            int colh = 64 + 8 * w + 2 * (lane & 3);
            uint32_t addr = hBase[wb] + (row * KP + colh) * 2;
            uint32_t pk = h2_u32(__floats2half2_rn(hv[0], hv[1]));
            asm volatile("st.shared.b32 [%0], %1;" :: "r"(addr), "r"(pk));
        }

        // Store prefetched x_{t+1}
        if (havex) {
            uint32_t p0 = h2_u32(__floats2half2_rn(xv.x, xv.y));
            uint32_t p1 = h2_u32(__floats2half2_rn(xv.z, xv.w));
            asm volatile("st.shared.v2.b32 [%0], {%1,%2};"
                         :: "r"(xBase[wb]), "r"(p0), "r"(p1));
        }

        __syncthreads();
    }

    // ---- Final projection: out[b,0:8] = tanh(h @ W_fc^T + b_fc) ----
    // After t=511 (wb=0), h_T is fp16 in Asm0 cols 64..191.
    if (tid < 256) {
        int row = tid >> 3;
        int a   = tid & 7;
        float accp = b_fc[a];
        const float* wf = W_fc + a * DIM_H;
        #pragma unroll 8
        for (int u = 0; u < DIM_H; ++u)
            accp += __half2float(Asm0[row * KP + 64 + u]) * wf[u];
        out[(size_t)(b0 + row) * 8 + a] = tanhf(accp);
    }
}

extern "C" void kernel_launch(void* const* d_in, const int* in_sizes, int n_in,
                              void* d_out, int out_size) {
    const float* state = (const float*)d_in[0];
    const float* W_ih  = (const float*)d_in[1];
    const float* W_hh  = (const float*)d_in[2];
    const float* b_ih  = (const float*)d_in[3];
    const float* b_hh  = (const float*)d_in[4];
    const float* W_fc  = (const float*)d_in[5];
    const float* b_fc  = (const float*)d_in[6];
    float* out = (float*)d_out;

    cudaFuncSetAttribute(lstm_fused_kernel,
                         cudaFuncAttributeMaxDynamicSharedMemorySize, SMEM_BYTES);

    lstm_fused_kernel<<<NBLOCKS, NTHREADS, SMEM_BYTES>>>(
        state, W_ih, W_hh, b_ih, b_hh, W_fc, b_fc, out);
}

// round 14
// speedup vs baseline: 1.2781x; 1.2113x over previous
#include <cuda_runtime.h>
#include <cuda_fp16.h>
#include <cstdint>

// LSTM scan, fused persistent kernel. v4: v3b + fast activations.
// Round-12 ncu (v3b): dur=1665us, occ=25%, issue=41.8%, tensor=40.7%,
// L1=44.2%. Warp-doubling gave only 5% -> phase convoy: MMA phase (LDS+tensor)
// then epilogue (MUFU ~3000cyc/step with exact EX2 sigmoid/tanh) run
// sequentially. Fix: tanh.approx-based activations (5 MUFU/unit vs 12);
// sigmoid(x) = 0.5*tanh(0.5x)+0.5. Error ~5e-4 per gate is same order as the
// existing fp16 h quantization; W_fc (+-0.003) attenuates h-error ~100x
// (measured rel_err 1.6e-5 vs per-step 2e-3 quantization), so safe vs 1e-3.
//
// B=4096, T=512, D=64, H=128, 4H=512.
//  - 128 CTAs x 512 threads (16 warps); CTA owns 32 batch rows for all steps.
//  - Wcat=[W_ih|W_hh] fp16 in smem [512][200]; A=[x|h] double-buffered,
//    ONE __syncthreads per step. gates = A @ Wcat^T via mma.sync.m16n8k16.
//  - fp32 cell state in regs.

namespace {
constexpr int T_STEPS  = 512;
constexpr int DIM_D    = 64;
constexpr int DIM_H    = 128;
constexpr int G4       = 512;
constexpr int KDIM     = 192;
constexpr int KP       = 200;   // padded row (400B, odd*16B -> conflict-free ldmatrix)
constexpr int BTILE    = 32;
constexpr int NTHREADS = 512;   // 16 warps
constexpr int NBLOCKS  = 128;
constexpr int ABUF     = BTILE * KP;
constexpr int SMEM_BYTES = (G4 * KP + 2 * ABUF) * 2;  // 230400 B < 232448 cap
}

__device__ __forceinline__ uint32_t smem_u32(const void* p) {
    return static_cast<uint32_t>(__cvta_generic_to_shared(p));
}
__device__ __forceinline__ uint32_t h2_u32(__half2 h) {
    return *reinterpret_cast<const uint32_t*>(&h);
}

// Fast activations: MUFU.TANH (1 op, ~5e-4 abs err, saturating -> no clamps).
__device__ __forceinline__ float tanh_fast(float x) {
    float y;
    asm("tanh.approx.f32 %0, %1;" : "=f"(y) : "f"(x));
    return y;
}
__device__ __forceinline__ float sigmoid_fast(float x) {
    return fmaf(0.5f, tanh_fast(0.5f * x), 0.5f);
}

__global__ void __launch_bounds__(NTHREADS, 1)
lstm_fused_kernel(const float* __restrict__ state,
                  const float* __restrict__ W_ih,
                  const float* __restrict__ W_hh,
                  const float* __restrict__ b_ih,
                  const float* __restrict__ b_hh,
                  const float* __restrict__ W_fc,
                  const float* __restrict__ b_fc,
                  float* __restrict__ out)
{
    extern __shared__ __half sm[];
    __half* Wsm  = sm;             // [G4][KP]
    __half* Asm0 = sm + G4 * KP;   // [BTILE][KP]
    __half* Asm1 = Asm0 + ABUF;

    const int tid  = threadIdx.x;
    const int w    = tid >> 5;     // warp 0..15
    const int lane = tid & 31;
    const int b0   = blockIdx.x * BTILE;

    // ---- Prologue: weights -> smem fp16; zero both A buffers ----
    for (int idx = tid; idx < G4 * KDIM; idx += NTHREADS) {
        int n = idx / KDIM;
        int k = idx - n * KDIM;
        float v = (k < DIM_D) ? W_ih[n * DIM_D + k] : W_hh[n * DIM_H + (k - DIM_D)];
        Wsm[n * KP + k] = __float2half_rn(v);
    }
    for (int idx = tid; idx < 2 * ABUF; idx += NTHREADS)
        Asm0[idx] = __ushort_as_half((unsigned short)0);

    // x-loader role: 512 threads cover 32 rows x 16 segments of 4 floats
    const int xrow = tid >> 4;          // 0..31
    const int xs4  = tid & 15;          // 0..15
    const float* xbase = state + (size_t)(b0 + xrow) * T_STEPS * DIM_D + xs4 * 4;

    __syncthreads();

    // x_0 into A buffer 0
    {
        float4 v = *(const float4*)(xbase);
        __half2* dst = (__half2*)&Asm0[xrow * KP + xs4 * 4];
        dst[0] = __floats2half2_rn(v.x, v.y);
        dst[1] = __floats2half2_rn(v.z, v.w);
    }

    // Per-thread bias: n-tile j = gate type (i,f,g,o); n_base(j) = 128*j + 8*w
    float biasr[4][2];
    #pragma unroll
    for (int j = 0; j < 4; ++j) {
        int nb = j * 128 + 8 * w + 2 * (lane & 3);
        biasr[j][0] = b_ih[nb]     + b_hh[nb];
        biasr[j][1] = b_ih[nb + 1] + b_hh[nb + 1];
    }

    // ldmatrix addresses
    uint32_t aAddr[2][2], bAddr[4];
    uint32_t hBase[2], xBase[2];
    {
        int ar = (lane & 7) + ((lane >> 3) & 1) * 8;
        int ac = (lane >> 4) * 8;
        aAddr[0][0] = smem_u32(&Asm0[ar * KP + ac]);
        aAddr[0][1] = smem_u32(&Asm0[(16 + ar) * KP + ac]);
        aAddr[1][0] = smem_u32(&Asm1[ar * KP + ac]);
        aAddr[1][1] = smem_u32(&Asm1[(16 + ar) * KP + ac]);
        hBase[0] = smem_u32(Asm0);
        hBase[1] = smem_u32(Asm1);
        xBase[0] = smem_u32(&Asm0[xrow * KP + xs4 * 4]);
        xBase[1] = smem_u32(&Asm1[xrow * KP + xs4 * 4]);
        int br = lane & 7;
        int bc = ((lane >> 3) & 1) * 8;
        #pragma unroll
        for (int j = 0; j < 4; ++j) {
            int nb0 = j * 128 + 8 * w;
            bAddr[j] = smem_u32(&Wsm[(nb0 + br) * KP + bc]);
        }
    }

    // fp32 cell state, 8 elems/thread: index (mi*4 + rh*2 + c)
    float cst[8];
    #pragma unroll
    for (int i = 0; i < 8; ++i) cst[i] = 0.f;

    __syncthreads();

    // ---- Time loop: read A[t&1], write A[(t+1)&1]; ONE barrier per step ----
    #pragma unroll 1
    for (int t = 0; t < T_STEPS; ++t) {
        const int rb = t & 1;
        const int wb = rb ^ 1;

        // Prefetch x_{t+1} (clamped, branchless; stored in epilogue)
        const bool havex = (t < T_STEPS - 1);
        const int  tn    = havex ? (t + 1) : t;
        float4 xv = *(const float4*)(xbase + (size_t)tn * DIM_D);

        // Accumulators from bias
        float acc[2][4][4];
        #pragma unroll
        for (int mi = 0; mi < 2; ++mi)
            #pragma unroll
            for (int j = 0; j < 4; ++j) {
                acc[mi][j][0] = biasr[j][0];
                acc[mi][j][1] = biasr[j][1];
                acc[mi][j][2] = biasr[j][0];
                acc[mi][j][3] = biasr[j][1];
            }

        // gates = A @ Wcat^T, K=192 in 12 k-tiles.
        // All 6 LDSMs issued before the 8 MMAs (asm volatile keeps program
        // order, so batching the loads is what lets HMMA overlap LDS latency).
        #pragma unroll
        for (int kt = 0; kt < 12; ++kt) {
            uint32_t a0[4], a1[4], bb[4][2];
            asm volatile("ldmatrix.sync.aligned.m8n8.x4.shared.b16 {%0,%1,%2,%3}, [%4];"
                         : "=r"(a0[0]), "=r"(a0[1]), "=r"(a0[2]), "=r"(a0[3])
                         : "r"(aAddr[rb][0] + kt * 32));
            asm volatile("ldmatrix.sync.aligned.m8n8.x4.shared.b16 {%0,%1,%2,%3}, [%4];"
                         : "=r"(a1[0]), "=r"(a1[1]), "=r"(a1[2]), "=r"(a1[3])
                         : "r"(aAddr[rb][1] + kt * 32));
            #pragma unroll
            for (int j = 0; j < 4; ++j)
                asm volatile("ldmatrix.sync.aligned.m8n8.x2.shared.b16 {%0,%1}, [%2];"
                             : "=r"(bb[j][0]), "=r"(bb[j][1])
                             : "r"(bAddr[j] + kt * 32));
            #pragma unroll
            for (int j = 0; j < 4; ++j) {
                asm volatile("mma.sync.aligned.m16n8k16.row.col.f32.f16.f16.f32 "
                             "{%0,%1,%2,%3},{%4,%5,%6,%7},{%8,%9},{%0,%1,%2,%3};"
                             : "+f"(acc[0][j][0]), "+f"(acc[0][j][1]),
                               "+f"(acc[0][j][2]), "+f"(acc[0][j][3])
                             : "r"(a0[0]), "r"(a0[1]), "r"(a0[2]), "r"(a0[3]),
                               "r"(bb[j][0]), "r"(bb[j][1]));
                asm volatile("mma.sync.aligned.m16n8k16.row.col.f32.f16.f16.f32 "
                             "{%0,%1,%2,%3},{%4,%5,%6,%7},{%8,%9},{%0,%1,%2,%3};"
                             : "+f"(acc[1][j][0]), "+f"(acc[1][j][1]),
                               "+f"(acc[1][j][2]), "+f"(acc[1][j][3])
                             : "r"(a1[0]), "r"(a1[1]), "r"(a1[2]), "r"(a1[3]),
                               "r"(bb[j][0]), "r"(bb[j][1]));
            }
        }

        // No mid-step barrier: writes go to the other buffer; the end-of-step
        // barrier of step t-1 ordered all reads of buf wb before these writes.

        // Epilogue: j=0..3 are i,f,g,o directly. 8 units/thread.
        // Fast path: 5 MUFU.TANH per unit (was 12 MUFU via EX2/RCP).
        #pragma unroll
        for (int mi = 0; mi < 2; ++mi)
        #pragma unroll
        for (int rh = 0; rh < 2; ++rh) {
            float hv[2];
            #pragma unroll
            for (int c = 0; c < 2; ++c) {
                int q = rh * 2 + c;
                float iv = sigmoid_fast(acc[mi][0][q]);
                float fv = sigmoid_fast(acc[mi][1][q]);
                float gv = tanh_fast   (acc[mi][2][q]);
                float ov = sigmoid_fast(acc[mi][3][q]);
                int ci = mi * 4 + rh * 2 + c;
                float cn = fv * cst[ci] + iv * gv;
                cst[ci] = cn;
                hv[c] = ov * tanh_fast(cn);
            }
            int row  = 16 * mi + (lane >> 2) + 8 * rh;
            int colh = 64 + 8 * w + 2 * (lane & 3);
            uint32_t addr = hBase[wb] + (row * KP + colh) * 2;
            uint32_t pk = h2_u32(__floats2half2_rn(hv[0], hv[1]));
            asm volatile("st.shared.b32 [%0], %1;" :: "r"(addr), "r"(pk));
        }

        // Store prefetched x_{t+1}
        if (havex) {
            uint32_t p0 = h2_u32(__floats2half2_rn(xv.x, xv.y));
            uint32_t p1 = h2_u32(__floats2half2_rn(xv.z, xv.w));
            asm volatile("st.shared.v2.b32 [%0], {%1,%2};"
                         :: "r"(xBase[wb]), "r"(p0), "r"(p1));
        }

        __syncthreads();
    }

    // ---- Final projection: out[b,0:8] = tanh(h @ W_fc^T + b_fc) ----
    // After t=511 (wb=0), h_T is fp16 in Asm0 cols 64..191.
    if (tid < 256) {
        int row = tid >> 3;
        int a   = tid & 7;
        float accp = b_fc[a];
        const float* wf = W_fc + a * DIM_H;
        #pragma unroll 8
        for (int u = 0; u < DIM_H; ++u)
            accp += __half2float(Asm0[row * KP + 64 + u]) * wf[u];
        out[(size_t)(b0 + row) * 8 + a] = tanhf(accp);
    }
}

extern "C" void kernel_launch(void* const* d_in, const int* in_sizes, int n_in,
                              void* d_out, int out_size) {
    const float* state = (const float*)d_in[0];
    const float* W_ih  = (const float*)d_in[1];
    const float* W_hh  = (const float*)d_in[2];
    const float* b_ih  = (const float*)d_in[3];
    const float* b_hh  = (const float*)d_in[4];
    const float* W_fc  = (const float*)d_in[5];
    const float* b_fc  = (const float*)d_in[6];
    float* out = (float*)d_out;

    cudaFuncSetAttribute(lstm_fused_kernel,
                         cudaFuncAttributeMaxDynamicSharedMemorySize, SMEM_BYTES);

    lstm_fused_kernel<<<NBLOCKS, NTHREADS, SMEM_BYTES>>>(
        state, W_ih, W_hh, b_ih, b_hh, W_fc, b_fc, out);
}